// round 6
// baseline (speedup 1.0000x reference)
#include <cuda_runtime.h>
#include <cuda_bf16.h>
#include <math.h>

#define N_NODES  100000
#define N_EDGES  3200000
#define D_FEAT   128
#define HIDDEN   64
#define N_GRAPHS 64
#define N_CLASSES 10

// ---------------- scratch (device globals; no allocation allowed) -----------
__device__ __align__(16) float g_deg[N_NODES];
__device__ __align__(16) float g_dinv[N_NODES];
__device__ __align__(16) float g_h[N_NODES * HIDDEN];     // transformed features (X@W)
__device__ __align__(16) float g_hin[N_NODES * HIDDEN];   // relu'd layer output
__device__ __align__(16) float g_agg[N_NODES * HIDDEN];   // scatter accumulator
__device__ __align__(16) float g_gsum[N_GRAPHS * HIDDEN];
__device__ __align__(16) float g_gcnt[N_GRAPHS];

// ---------------- degree / norm ---------------------------------------------
__global__ void k_init_deg() {
    int i = blockIdx.x * blockDim.x + threadIdx.x;
    if (i < N_NODES) g_deg[i] = 1.0f;   // self-loop
}

__global__ void k_deg_edges(const int* __restrict__ dst) {
    int e = blockIdx.x * blockDim.x + threadIdx.x;
    if (e < N_EDGES) atomicAdd(&g_deg[dst[e]], 1.0f);
}

__global__ void k_dinv() {
    int i = blockIdx.x * blockDim.x + threadIdx.x;
    if (i < N_NODES) g_dinv[i] = rsqrtf(g_deg[i]);   // deg >= 1 always
}

// ---------------- dense GEMM: Y[N,64] = X[N,K] @ W[K,64] --------------------
// Block computes 32 rows x 64 cols. Thread tile: 4 rows x 2 cols (c, c+32).
template <int K>
__global__ void k_gemm(const float* __restrict__ X, const float* __restrict__ W,
                       float* __restrict__ Y) {
    __shared__ float Ws[K * 64];
    __shared__ float Xs[32 * K];
    const int t = threadIdx.x;
    const int row0 = blockIdx.x * 32;

    for (int i = t; i < K * 64; i += 256) Ws[i] = W[i];
    for (int i = t; i < 32 * K; i += 256) Xs[i] = X[(size_t)row0 * K + i];
    __syncthreads();

    const int c0 = t & 31;          // cols c0 and c0+32 (conflict-free Ws reads)
    const int r0 = (t >> 5) * 4;    // 4 consecutive local rows

    float acc[4][2] = {};
#pragma unroll 4
    for (int k = 0; k < K; k++) {
        float w0 = Ws[k * 64 + c0];
        float w1 = Ws[k * 64 + c0 + 32];
#pragma unroll
        for (int i = 0; i < 4; i++) {
            float xv = Xs[(r0 + i) * K + k];
            acc[i][0] += xv * w0;
            acc[i][1] += xv * w1;
        }
    }
#pragma unroll
    for (int i = 0; i < 4; i++) {
        size_t base = (size_t)(row0 + r0 + i) * 64;
        Y[base + c0]      = acc[i][0];
        Y[base + c0 + 32] = acc[i][1];
    }
}

// ---------------- self-loop init: agg = h * dinv^2 --------------------------
__global__ void k_self_init(const float* __restrict__ h) {
    int i = blockIdx.x * blockDim.x + threadIdx.x;   // over N*H/4 float4 chunks
    if (i >= N_NODES * HIDDEN / 4) return;
    int node = i / (HIDDEN / 4);
    float s = g_dinv[node]; s *= s;
    float4 v = reinterpret_cast<const float4*>(h)[i];
    v.x *= s; v.y *= s; v.z *= s; v.w *= s;
    reinterpret_cast<float4*>(g_agg)[i] = v;
}

// ---------------- edge scatter: agg[dst] += h[src] * dinv[s]*dinv[d] --------
// 16 threads per edge, one float4 gather each; 4 scalar atomicAdd (-> REDG).
__global__ void k_scatter(const int* __restrict__ src,
                          const int* __restrict__ dst,
                          const float* __restrict__ h) {
    long long tid = (long long)blockIdx.x * blockDim.x + threadIdx.x;
    int e = (int)(tid >> 4);
    if (e >= N_EDGES) return;
    int c = (int)(tid & 15);
    int s = src[e];
    int d = dst[e];
    float w = g_dinv[s] * g_dinv[d];
    float4 v = *reinterpret_cast<const float4*>(h + (size_t)s * 64 + c * 4);
    float* p = g_agg + (size_t)d * 64 + c * 4;
    atomicAdd(p + 0, v.x * w);
    atomicAdd(p + 1, v.y * w);
    atomicAdd(p + 2, v.z * w);
    atomicAdd(p + 3, v.w * w);
}

// ---------------- bias + relu: hin = relu(agg + b) ---------------------------
__global__ void k_bias_relu(const float* __restrict__ b) {
    int i = blockIdx.x * blockDim.x + threadIdx.x;   // over N*H/4 float4 chunks
    if (i >= N_NODES * HIDDEN / 4) return;
    int f4 = i & (HIDDEN / 4 - 1);
    float4 bb = reinterpret_cast<const float4*>(b)[f4];
    float4 v = reinterpret_cast<const float4*>(g_agg)[i];
    v.x = fmaxf(v.x + bb.x, 0.f);
    v.y = fmaxf(v.y + bb.y, 0.f);
    v.z = fmaxf(v.z + bb.z, 0.f);
    v.w = fmaxf(v.w + bb.w, 0.f);
    reinterpret_cast<float4*>(g_hin)[i] = v;
}

// ---------------- pooling ----------------------------------------------------
__global__ void k_pool_zero() {
    int i = blockIdx.x * blockDim.x + threadIdx.x;
    if (i < N_GRAPHS * HIDDEN) g_gsum[i] = 0.f;
    if (i < N_GRAPHS) g_gcnt[i] = 0.f;
}

// batch is sorted -> run-length accumulate per block, flush on graph change.
// Applies bias b2 + relu inline (layer-2 epilogue fused here).
__global__ void k_pool(const int* __restrict__ batch,
                       const float* __restrict__ b2) {
    const int f = threadIdx.x;  // 0..63
    const int chunk = (N_NODES + gridDim.x - 1) / gridDim.x;
    int n0 = blockIdx.x * chunk;
    if (n0 >= N_NODES) return;
    int n1 = min(n0 + chunk, N_NODES);

    const float bf = b2[f];
    int cur = batch[n0];
    float acc = 0.f, cnt = 0.f;
    for (int n = n0; n < n1; n++) {
        int bt = batch[n];
        if (bt != cur) {
            atomicAdd(&g_gsum[cur * HIDDEN + f], acc);
            if (f == 0) atomicAdd(&g_gcnt[cur], cnt);
            acc = 0.f; cnt = 0.f; cur = bt;
        }
        acc += fmaxf(g_agg[(size_t)n * HIDDEN + f] + bf, 0.f);
        cnt += 1.f;
    }
    atomicAdd(&g_gsum[cur * HIDDEN + f], acc);
    if (f == 0) atomicAdd(&g_gcnt[cur], cnt);
}

// ---------------- head: mean, linear, log_softmax ----------------------------
__global__ void k_head(const float* __restrict__ linW, const float* __restrict__ linb,
                       float* __restrict__ out) {
    int g = threadIdx.x;
    if (g >= N_GRAPHS) return;
    float inv = 1.0f / fmaxf(g_gcnt[g], 1.0f);
    float logits[N_CLASSES];
#pragma unroll
    for (int c = 0; c < N_CLASSES; c++) logits[c] = linb[c];
    for (int f = 0; f < HIDDEN; f++) {
        float p = g_gsum[g * HIDDEN + f] * inv;
#pragma unroll
        for (int c = 0; c < N_CLASSES; c++) logits[c] += p * linW[f * N_CLASSES + c];
    }
    float m = logits[0];
#pragma unroll
    for (int c = 1; c < N_CLASSES; c++) m = fmaxf(m, logits[c]);
    float s = 0.f;
#pragma unroll
    for (int c = 0; c < N_CLASSES; c++) s += expf(logits[c] - m);
    float l = logf(s) + m;
#pragma unroll
    for (int c = 0; c < N_CLASSES; c++) out[g * N_CLASSES + c] = logits[c] - l;
}

// ---------------- launch ------------------------------------------------------
extern "C" void kernel_launch(void* const* d_in, const int* in_sizes, int n_in,
                              void* d_out, int out_size) {
    const float* x     = (const float*)d_in[0];
    const int*   ei    = (const int*)d_in[1];     // JAX x64 disabled -> int32
    const int*   batch = (const int*)d_in[2];
    const float* W1    = (const float*)d_in[3];
    const float* b1    = (const float*)d_in[4];
    const float* W2    = (const float*)d_in[5];
    const float* b2    = (const float*)d_in[6];
    const float* linW  = (const float*)d_in[7];
    const float* linb  = (const float*)d_in[8];
    float* out = (float*)d_out;

    const int* src = ei;
    const int* dst = ei + N_EDGES;

    float *p_h, *p_hin;
    cudaGetSymbolAddress((void**)&p_h, g_h);
    cudaGetSymbolAddress((void**)&p_hin, g_hin);

    const int NT = 256;
    const int nodeBlocks = (N_NODES + NT - 1) / NT;
    const int edgeBlocks = (N_EDGES + NT - 1) / NT;
    const int featChunks = N_NODES * HIDDEN / 4;
    const int featBlocks = (featChunks + NT - 1) / NT;
    const long long scatterThreads = (long long)N_EDGES * 16;
    const int scatterBlocks = (int)((scatterThreads + NT - 1) / NT);

    // normalization
    k_init_deg<<<nodeBlocks, NT>>>();
    k_deg_edges<<<edgeBlocks, NT>>>(dst);
    k_dinv<<<nodeBlocks, NT>>>();

    // layer 1: h = x@W1 ; agg = scatter(norm * h) ; hin = relu(agg + b1)
    k_gemm<D_FEAT><<<N_NODES / 32, NT>>>(x, W1, p_h);
    k_self_init<<<featBlocks, NT>>>(p_h);
    k_scatter<<<scatterBlocks, NT>>>(src, dst, p_h);
    k_bias_relu<<<featBlocks, NT>>>(b1);

    // layer 2: h = hin@W2 ; agg = scatter(norm * h)   (bias+relu fused in pool)
    k_gemm<HIDDEN><<<N_NODES / 32, NT>>>(p_hin, W2, p_h);
    k_self_init<<<featBlocks, NT>>>(p_h);
    k_scatter<<<scatterBlocks, NT>>>(src, dst, p_h);

    // pooling + head
    k_pool_zero<<<(N_GRAPHS * HIDDEN + NT - 1) / NT, NT>>>();
    k_pool<<<1024, HIDDEN>>>(batch, b2);
    k_head<<<1, N_GRAPHS>>>(linW, linb, out);
}

// round 7
// speedup vs baseline: 2.0928x; 2.0928x over previous
#include <cuda_runtime.h>
#include <cuda_bf16.h>
#include <math.h>

#define N_NODES  100000
#define N_EDGES  3200000
#define D_FEAT   128
#define HIDDEN   64
#define N_GRAPHS 64
#define N_CLASSES 10

// ---------------- scratch (device globals; no allocation allowed) -----------
__device__ __align__(16) float g_deg[N_NODES];
__device__ __align__(16) float g_dinv[N_NODES];
__device__ __align__(16) float g_h[N_NODES * HIDDEN];    // pre-scaled h' = (X@W)*dinv[row]
__device__ __align__(16) float g_agg1[N_NODES * HIDDEN]; // layer-1 aggregate
__device__ __align__(16) float g_agg2[N_NODES * HIDDEN]; // layer-2 aggregate
__device__ __align__(16) float g_gsum[N_GRAPHS * HIDDEN];
__device__ __align__(16) float g_gcnt[N_GRAPHS];

// ---------------- degree / norm ---------------------------------------------
__global__ void k_init_deg() {
    int i = blockIdx.x * blockDim.x + threadIdx.x;
    if (i < N_NODES) g_deg[i] = 1.0f;   // self-loop
}

__global__ void k_deg_edges(const int* __restrict__ dst) {
    int e = blockIdx.x * blockDim.x + threadIdx.x;
    if (e < N_EDGES) atomicAdd(&g_deg[dst[e]], 1.0f);
}

__global__ void k_dinv() {
    int i = blockIdx.x * blockDim.x + threadIdx.x;
    if (i < N_NODES) g_dinv[i] = rsqrtf(g_deg[i]);   // deg >= 1 always
}

// ---------------- GEMM: 64x64 block tile, 4x4 thread tile --------------------
// Computes h' = (X@W) * dinv[row]  and  agg_init = h' * dinv[row]  (self-loop).
// RELU path applies relu(x + bias) to the input on the fly (layer-2 fusion).
template <int K, bool RELU>
__global__ void k_gemm(const float* __restrict__ X, const float* __restrict__ W,
                       const float* __restrict__ bias,
                       float* __restrict__ Hs, float* __restrict__ Agg) {
    __shared__ float Ws[64][64];   // [k][col] chunk
    __shared__ float Xt[64][68];   // [k][row] chunk, padded (68*4B = 16B-aligned rows)

    const int t = threadIdx.x;
    const int row0 = blockIdx.x * 64;
    const int tc = (t & 15) * 4;   // 4 consecutive cols
    const int tr = (t >> 4) * 4;   // 4 consecutive rows

    float acc[4][4] = {};

    for (int k0 = 0; k0 < K; k0 += 64) {
        __syncthreads();   // protect smem reuse across chunks
        // load W chunk [64k x 64c], coalesced
        #pragma unroll 4
        for (int i = t; i < 64 * 64; i += 256) {
            int k = i >> 6, c = i & 63;
            Ws[k][c] = W[(size_t)(k0 + k) * 64 + c];
        }
        // load X chunk transposed: Xt[k][r] = X[row0+r][k0+k] (coalesced on k)
        #pragma unroll 4
        for (int i = t; i < 64 * 64; i += 256) {
            int r = i >> 6, k = i & 63;
            int gr = row0 + r;
            float v = 0.f;
            if (gr < N_NODES) {
                v = X[(size_t)gr * K + k0 + k];
                if (RELU) v = fmaxf(v + __ldg(&bias[k0 + k]), 0.f);
            }
            Xt[k][r] = v;
        }
        __syncthreads();

        #pragma unroll 16
        for (int k = 0; k < 64; k++) {
            float4 wv = *reinterpret_cast<const float4*>(&Ws[k][tc]);
            float4 xv = *reinterpret_cast<const float4*>(&Xt[k][tr]);
            acc[0][0] += xv.x * wv.x; acc[0][1] += xv.x * wv.y;
            acc[0][2] += xv.x * wv.z; acc[0][3] += xv.x * wv.w;
            acc[1][0] += xv.y * wv.x; acc[1][1] += xv.y * wv.y;
            acc[1][2] += xv.y * wv.z; acc[1][3] += xv.y * wv.w;
            acc[2][0] += xv.z * wv.x; acc[2][1] += xv.z * wv.y;
            acc[2][2] += xv.z * wv.z; acc[2][3] += xv.z * wv.w;
            acc[3][0] += xv.w * wv.x; acc[3][1] += xv.w * wv.y;
            acc[3][2] += xv.w * wv.z; acc[3][3] += xv.w * wv.w;
        }
    }

    #pragma unroll
    for (int i = 0; i < 4; i++) {
        int gr = row0 + tr + i;
        if (gr < N_NODES) {
            float dv = g_dinv[gr];
            float4 hp = make_float4(acc[i][0] * dv, acc[i][1] * dv,
                                    acc[i][2] * dv, acc[i][3] * dv);
            *reinterpret_cast<float4*>(&Hs[(size_t)gr * 64 + tc]) = hp;
            float4 ag = make_float4(hp.x * dv, hp.y * dv, hp.z * dv, hp.w * dv);
            *reinterpret_cast<float4*>(&Agg[(size_t)gr * 64 + tc]) = ag;
        }
    }
}

// ---------------- edge scatter: agg[dst] += h'[src] * dinv[d] ----------------
// 16 threads per edge, one float4 each; vector red.global (4x fewer LTS ops).
__global__ void k_scatter(const int* __restrict__ src,
                          const int* __restrict__ dst,
                          const float* __restrict__ h,
                          float* __restrict__ agg) {
    unsigned long long tid = (unsigned long long)blockIdx.x * blockDim.x + threadIdx.x;
    unsigned int e = (unsigned int)(tid >> 4);
    if (e >= N_EDGES) return;
    int c = ((int)tid & 15) << 2;
    int s = src[e];
    int d = dst[e];
    float w = g_dinv[d];
    float4 v = *reinterpret_cast<const float4*>(h + (size_t)s * 64 + c);
    float* p = agg + (size_t)d * 64 + c;
    unsigned long long gp;
    asm("cvta.to.global.u64 %0, %1;" : "=l"(gp) : "l"(p));
    asm volatile("red.global.add.v4.f32 [%0], {%1, %2, %3, %4};"
                 :: "l"(gp), "f"(v.x * w), "f"(v.y * w), "f"(v.z * w), "f"(v.w * w)
                 : "memory");
}

// ---------------- pooling ----------------------------------------------------
__global__ void k_pool_zero() {
    int i = blockIdx.x * blockDim.x + threadIdx.x;
    if (i < N_GRAPHS * HIDDEN) g_gsum[i] = 0.f;
    if (i < N_GRAPHS) g_gcnt[i] = 0.f;
}

// batch is sorted -> run-length accumulate per block, flush on graph change.
// Applies bias b2 + relu inline (layer-2 epilogue fused here).
__global__ void k_pool(const int* __restrict__ batch,
                       const float* __restrict__ b2,
                       const float* __restrict__ agg) {
    const int f = threadIdx.x;  // 0..63
    const int chunk = (N_NODES + gridDim.x - 1) / gridDim.x;
    int n0 = blockIdx.x * chunk;
    if (n0 >= N_NODES) return;
    int n1 = min(n0 + chunk, N_NODES);

    const float bf = b2[f];
    int cur = batch[n0];
    float acc = 0.f, cnt = 0.f;
    for (int n = n0; n < n1; n++) {
        int bt = batch[n];
        if (bt != cur) {
            atomicAdd(&g_gsum[cur * HIDDEN + f], acc);
            if (f == 0) atomicAdd(&g_gcnt[cur], cnt);
            acc = 0.f; cnt = 0.f; cur = bt;
        }
        acc += fmaxf(agg[(size_t)n * HIDDEN + f] + bf, 0.f);
        cnt += 1.f;
    }
    atomicAdd(&g_gsum[cur * HIDDEN + f], acc);
    if (f == 0) atomicAdd(&g_gcnt[cur], cnt);
}

// ---------------- head: mean, linear, log_softmax ----------------------------
__global__ void k_head(const float* __restrict__ linW, const float* __restrict__ linb,
                       float* __restrict__ out) {
    int g = threadIdx.x;
    if (g >= N_GRAPHS) return;
    float inv = 1.0f / fmaxf(g_gcnt[g], 1.0f);
    float logits[N_CLASSES];
#pragma unroll
    for (int c = 0; c < N_CLASSES; c++) logits[c] = linb[c];
    for (int f = 0; f < HIDDEN; f++) {
        float p = g_gsum[g * HIDDEN + f] * inv;
#pragma unroll
        for (int c = 0; c < N_CLASSES; c++) logits[c] += p * linW[f * N_CLASSES + c];
    }
    float m = logits[0];
#pragma unroll
    for (int c = 1; c < N_CLASSES; c++) m = fmaxf(m, logits[c]);
    float s = 0.f;
#pragma unroll
    for (int c = 0; c < N_CLASSES; c++) s += expf(logits[c] - m);
    float l = logf(s) + m;
#pragma unroll
    for (int c = 0; c < N_CLASSES; c++) out[g * N_CLASSES + c] = logits[c] - l;
}

// ---------------- launch ------------------------------------------------------
extern "C" void kernel_launch(void* const* d_in, const int* in_sizes, int n_in,
                              void* d_out, int out_size) {
    const float* x     = (const float*)d_in[0];
    const int*   ei    = (const int*)d_in[1];     // int32 (JAX x64 disabled)
    const int*   batch = (const int*)d_in[2];
    const float* W1    = (const float*)d_in[3];
    const float* b1    = (const float*)d_in[4];
    const float* W2    = (const float*)d_in[5];
    const float* b2    = (const float*)d_in[6];
    const float* linW  = (const float*)d_in[7];
    const float* linb  = (const float*)d_in[8];
    float* out = (float*)d_out;

    const int* src = ei;
    const int* dst = ei + N_EDGES;

    float *p_h, *p_agg1, *p_agg2;
    cudaGetSymbolAddress((void**)&p_h, g_h);
    cudaGetSymbolAddress((void**)&p_agg1, g_agg1);
    cudaGetSymbolAddress((void**)&p_agg2, g_agg2);

    const int NT = 256;
    const int nodeBlocks = (N_NODES + NT - 1) / NT;
    const int edgeBlocks = (N_EDGES + NT - 1) / NT;
    const int gemmBlocks = (N_NODES + 63) / 64;
    const long long scatterThreads = (long long)N_EDGES * 16;
    const int scatterBlocks = (int)((scatterThreads + NT - 1) / NT);

    // normalization
    k_init_deg<<<nodeBlocks, NT>>>();
    k_deg_edges<<<edgeBlocks, NT>>>(dst);
    k_dinv<<<nodeBlocks, NT>>>();

    // layer 1: h' = (x@W1)*dinv ; agg1 = h'*dinv (self) ; agg1 += scatter(h'*dinv[d])
    k_gemm<D_FEAT, false><<<gemmBlocks, NT>>>(x, W1, nullptr, p_h, p_agg1);
    k_scatter<<<scatterBlocks, NT>>>(src, dst, p_h, p_agg1);

    // layer 2: X = relu(agg1 + b1) fused into GEMM load
    k_gemm<HIDDEN, true><<<gemmBlocks, NT>>>(p_agg1, W2, b1, p_h, p_agg2);
    k_scatter<<<scatterBlocks, NT>>>(src, dst, p_h, p_agg2);

    // pooling (bias b2 + relu fused) + head
    k_pool_zero<<<(N_GRAPHS * HIDDEN + NT - 1) / NT, NT>>>();
    k_pool<<<1024, HIDDEN>>>(batch, b2, p_agg2);
    k_head<<<1, N_GRAPHS>>>(linW, linb, out);
}

// round 8
// speedup vs baseline: 3.5334x; 1.6883x over previous
#include <cuda_runtime.h>
#include <cuda_bf16.h>
#include <math.h>

#define N_NODES  100000
#define N_EDGES  3200000
#define D_FEAT   128
#define HIDDEN   64
#define N_GRAPHS 64
#define N_CLASSES 10
#define NBLK     391   // ceil(N_NODES/256)

// ---------------- scratch (device globals; no allocation allowed) -----------
__device__ __align__(16) float g_dinv[N_NODES];
__device__ __align__(16) float g_h[N_NODES * HIDDEN];    // h' = (X@W)*dinv[row]
__device__ __align__(16) float g_agg1[N_NODES * HIDDEN];
__device__ __align__(16) float g_agg2[N_NODES * HIDDEN];
__device__ __align__(16) float g_gsum[N_GRAPHS * HIDDEN];
__device__ __align__(16) float g_gcnt[N_GRAPHS];
// CSR scratch
__device__ int g_cnt[N_NODES];
__device__ int g_incl[N_NODES];
__device__ int g_bsum[NBLK];
__device__ int g_bsumx[NBLK];
__device__ int g_off[N_NODES + 1];
__device__ int g_cur[N_NODES];
__device__ __align__(16) int g_ssrc[N_EDGES];

// ---------------- CSR build ---------------------------------------------------
__global__ void k_zero_cnt() {
    int i = blockIdx.x * blockDim.x + threadIdx.x;
    if (i < N_NODES) g_cnt[i] = 0;
}

__global__ void k_hist(const int* __restrict__ dst) {
    int e = blockIdx.x * blockDim.x + threadIdx.x;
    if (e < N_EDGES) atomicAdd(&g_cnt[dst[e]], 1);
}

// local inclusive scan per 256-block
__global__ void k_scan_local() {
    __shared__ int sm[256];
    int i = blockIdx.x * 256 + threadIdx.x;
    int v = (i < N_NODES) ? g_cnt[i] : 0;
    sm[threadIdx.x] = v;
    __syncthreads();
    #pragma unroll
    for (int ofs = 1; ofs < 256; ofs <<= 1) {
        int t = (threadIdx.x >= ofs) ? sm[threadIdx.x - ofs] : 0;
        __syncthreads();
        sm[threadIdx.x] += t;
        __syncthreads();
    }
    if (i < N_NODES) g_incl[i] = sm[threadIdx.x];
    if (threadIdx.x == 255) g_bsum[blockIdx.x] = sm[255];
}

// scan the 391 block sums (single block)
__global__ void k_scan_blocks() {
    __shared__ int sm[512];
    int t = threadIdx.x;
    int orig = (t < NBLK) ? g_bsum[t] : 0;
    sm[t] = orig;
    __syncthreads();
    #pragma unroll
    for (int ofs = 1; ofs < 512; ofs <<= 1) {
        int v = (t >= ofs) ? sm[t - ofs] : 0;
        __syncthreads();
        sm[t] += v;
        __syncthreads();
    }
    if (t < NBLK) g_bsumx[t] = sm[t] - orig;   // exclusive
    if (t == 0) g_off[N_NODES] = N_EDGES;
}

// offsets + cursors + dinv
__global__ void k_finalize() {
    int i = blockIdx.x * blockDim.x + threadIdx.x;
    if (i >= N_NODES) return;
    int c = g_cnt[i];
    int o = g_bsumx[i >> 8] + g_incl[i] - c;   // exclusive global offset
    g_off[i] = o;
    g_cur[i] = o;
    g_dinv[i] = rsqrtf((float)(c + 1));        // +1 self loop
}

__global__ void k_fill(const int* __restrict__ src, const int* __restrict__ dst) {
    int e = blockIdx.x * blockDim.x + threadIdx.x;
    if (e >= N_EDGES) return;
    int d = dst[e];
    int slot = atomicAdd(&g_cur[d], 1);
    g_ssrc[slot] = src[e];
}

// ---------------- GEMM: 64x64 block tile, 4x4 thread tile --------------------
// Computes h' = (X@W) * dinv[row]. RELU path applies relu(x + bias) on load.
template <int K, bool RELU>
__global__ void k_gemm(const float* __restrict__ X, const float* __restrict__ W,
                       const float* __restrict__ bias, float* __restrict__ Hs) {
    __shared__ float Ws[64][64];
    __shared__ float Xt[64][68];

    const int t = threadIdx.x;
    const int row0 = blockIdx.x * 64;
    const int tc = (t & 15) * 4;
    const int tr = (t >> 4) * 4;

    float acc[4][4] = {};

    for (int k0 = 0; k0 < K; k0 += 64) {
        __syncthreads();
        #pragma unroll 4
        for (int i = t; i < 64 * 64; i += 256) {
            int k = i >> 6, c = i & 63;
            Ws[k][c] = W[(size_t)(k0 + k) * 64 + c];
        }
        #pragma unroll 4
        for (int i = t; i < 64 * 64; i += 256) {
            int r = i >> 6, k = i & 63;
            int gr = row0 + r;
            float v = 0.f;
            if (gr < N_NODES) {
                v = X[(size_t)gr * K + k0 + k];
                if (RELU) v = fmaxf(v + __ldg(&bias[k0 + k]), 0.f);
            }
            Xt[k][r] = v;
        }
        __syncthreads();

        #pragma unroll 16
        for (int k = 0; k < 64; k++) {
            float4 wv = *reinterpret_cast<const float4*>(&Ws[k][tc]);
            float4 xv = *reinterpret_cast<const float4*>(&Xt[k][tr]);
            acc[0][0] += xv.x * wv.x; acc[0][1] += xv.x * wv.y;
            acc[0][2] += xv.x * wv.z; acc[0][3] += xv.x * wv.w;
            acc[1][0] += xv.y * wv.x; acc[1][1] += xv.y * wv.y;
            acc[1][2] += xv.y * wv.z; acc[1][3] += xv.y * wv.w;
            acc[2][0] += xv.z * wv.x; acc[2][1] += xv.z * wv.y;
            acc[2][2] += xv.z * wv.z; acc[2][3] += xv.z * wv.w;
            acc[3][0] += xv.w * wv.x; acc[3][1] += xv.w * wv.y;
            acc[3][2] += xv.w * wv.z; acc[3][3] += xv.w * wv.w;
        }
    }

    #pragma unroll
    for (int i = 0; i < 4; i++) {
        int gr = row0 + tr + i;
        if (gr < N_NODES) {
            float dv = g_dinv[gr];
            float4 hp = make_float4(acc[i][0] * dv, acc[i][1] * dv,
                                    acc[i][2] * dv, acc[i][3] * dv);
            *reinterpret_cast<float4*>(&Hs[(size_t)gr * 64 + tc]) = hp;
        }
    }
}

// ---------------- pull aggregation: agg[d] = dinv[d]*(h'[d] + sum h'[src]) ----
// 16 threads per node, one float4 column each; 4-way pipelined gather, no atomics.
__global__ void k_gather(const float* __restrict__ h, float* __restrict__ agg) {
    int tid = blockIdx.x * blockDim.x + threadIdx.x;
    int node = tid >> 4;
    if (node >= N_NODES) return;
    int c4 = tid & 15;                       // float4 column index
    const float4* hp = reinterpret_cast<const float4*>(h);

    int beg = g_off[node];
    int end = g_off[node + 1];

    float4 acc = hp[(size_t)node * 16 + c4];  // self term (h' already has dinv[node])
    int j = beg;
    for (; j + 4 <= end; j += 4) {
        int s0 = g_ssrc[j];
        int s1 = g_ssrc[j + 1];
        int s2 = g_ssrc[j + 2];
        int s3 = g_ssrc[j + 3];
        float4 v0 = hp[(size_t)s0 * 16 + c4];
        float4 v1 = hp[(size_t)s1 * 16 + c4];
        float4 v2 = hp[(size_t)s2 * 16 + c4];
        float4 v3 = hp[(size_t)s3 * 16 + c4];
        acc.x += (v0.x + v1.x) + (v2.x + v3.x);
        acc.y += (v0.y + v1.y) + (v2.y + v3.y);
        acc.z += (v0.z + v1.z) + (v2.z + v3.z);
        acc.w += (v0.w + v1.w) + (v2.w + v3.w);
    }
    for (; j < end; j++) {
        int s = g_ssrc[j];
        float4 v = hp[(size_t)s * 16 + c4];
        acc.x += v.x; acc.y += v.y; acc.z += v.z; acc.w += v.w;
    }
    float dv = g_dinv[node];
    acc.x *= dv; acc.y *= dv; acc.z *= dv; acc.w *= dv;
    reinterpret_cast<float4*>(agg)[(size_t)node * 16 + c4] = acc;
}

// ---------------- pooling ----------------------------------------------------
__global__ void k_pool_zero() {
    int i = blockIdx.x * blockDim.x + threadIdx.x;
    if (i < N_GRAPHS * HIDDEN) g_gsum[i] = 0.f;
    if (i < N_GRAPHS) g_gcnt[i] = 0.f;
}

__global__ void k_pool(const int* __restrict__ batch,
                       const float* __restrict__ b2,
                       const float* __restrict__ agg) {
    const int f = threadIdx.x;  // 0..63
    const int chunk = (N_NODES + gridDim.x - 1) / gridDim.x;
    int n0 = blockIdx.x * chunk;
    if (n0 >= N_NODES) return;
    int n1 = min(n0 + chunk, N_NODES);

    const float bf = b2[f];
    int cur = batch[n0];
    float acc = 0.f, cnt = 0.f;
    for (int n = n0; n < n1; n++) {
        int bt = batch[n];
        if (bt != cur) {
            atomicAdd(&g_gsum[cur * HIDDEN + f], acc);
            if (f == 0) atomicAdd(&g_gcnt[cur], cnt);
            acc = 0.f; cnt = 0.f; cur = bt;
        }
        acc += fmaxf(agg[(size_t)n * HIDDEN + f] + bf, 0.f);
        cnt += 1.f;
    }
    atomicAdd(&g_gsum[cur * HIDDEN + f], acc);
    if (f == 0) atomicAdd(&g_gcnt[cur], cnt);
}

// ---------------- head: mean, linear, log_softmax ----------------------------
__global__ void k_head(const float* __restrict__ linW, const float* __restrict__ linb,
                       float* __restrict__ out) {
    int g = threadIdx.x;
    if (g >= N_GRAPHS) return;
    float inv = 1.0f / fmaxf(g_gcnt[g], 1.0f);
    float logits[N_CLASSES];
#pragma unroll
    for (int c = 0; c < N_CLASSES; c++) logits[c] = linb[c];
    for (int f = 0; f < HIDDEN; f++) {
        float p = g_gsum[g * HIDDEN + f] * inv;
#pragma unroll
        for (int c = 0; c < N_CLASSES; c++) logits[c] += p * linW[f * N_CLASSES + c];
    }
    float m = logits[0];
#pragma unroll
    for (int c = 1; c < N_CLASSES; c++) m = fmaxf(m, logits[c]);
    float s = 0.f;
#pragma unroll
    for (int c = 0; c < N_CLASSES; c++) s += expf(logits[c] - m);
    float l = logf(s) + m;
#pragma unroll
    for (int c = 0; c < N_CLASSES; c++) out[g * N_CLASSES + c] = logits[c] - l;
}

// ---------------- launch ------------------------------------------------------
extern "C" void kernel_launch(void* const* d_in, const int* in_sizes, int n_in,
                              void* d_out, int out_size) {
    const float* x     = (const float*)d_in[0];
    const int*   ei    = (const int*)d_in[1];
    const int*   batch = (const int*)d_in[2];
    const float* W1    = (const float*)d_in[3];
    const float* b1    = (const float*)d_in[4];
    const float* W2    = (const float*)d_in[5];
    const float* b2    = (const float*)d_in[6];
    const float* linW  = (const float*)d_in[7];
    const float* linb  = (const float*)d_in[8];
    float* out = (float*)d_out;

    const int* src = ei;
    const int* dst = ei + N_EDGES;

    float *p_h, *p_agg1, *p_agg2;
    cudaGetSymbolAddress((void**)&p_h, g_h);
    cudaGetSymbolAddress((void**)&p_agg1, g_agg1);
    cudaGetSymbolAddress((void**)&p_agg2, g_agg2);

    const int NT = 256;
    const int nodeBlocks = NBLK;
    const int edgeBlocks = (N_EDGES + NT - 1) / NT;
    const int gemmBlocks = (N_NODES + 63) / 64;
    const int gatherBlocks = (N_NODES * 16 + NT - 1) / NT;

    // CSR build (reused by both layers)
    k_zero_cnt<<<nodeBlocks, NT>>>();
    k_hist<<<edgeBlocks, NT>>>(dst);
    k_scan_local<<<NBLK, 256>>>();
    k_scan_blocks<<<1, 512>>>();
    k_finalize<<<nodeBlocks, NT>>>();
    k_fill<<<edgeBlocks, NT>>>(src, dst);

    // layer 1
    k_gemm<D_FEAT, false><<<gemmBlocks, NT>>>(x, W1, nullptr, p_h);
    k_gather<<<gatherBlocks, NT>>>(p_h, p_agg1);

    // layer 2 (relu + b1 fused into GEMM load)
    k_gemm<HIDDEN, true><<<gemmBlocks, NT>>>(p_agg1, W2, b1, p_h);
    k_gather<<<gatherBlocks, NT>>>(p_h, p_agg2);

    // pooling (b2 + relu fused) + head
    k_pool_zero<<<(N_GRAPHS * HIDDEN + NT - 1) / NT, NT>>>();
    k_pool<<<1024, HIDDEN>>>(batch, b2, p_agg2);
    k_head<<<1, N_GRAPHS>>>(linW, linb, out);
}

// round 9
// speedup vs baseline: 3.5646x; 1.0088x over previous
#include <cuda_runtime.h>
#include <cuda_bf16.h>
#include <math.h>

#define N_NODES  100000
#define N_EDGES  3200000
#define D_FEAT   128
#define HIDDEN   64
#define N_GRAPHS 64
#define N_CLASSES 10
#define NBLK     391   // ceil(N_NODES/256)

// ---------------- scratch (device globals; no allocation allowed) -----------
__device__ __align__(16) float g_dinv[N_NODES];
__device__ __align__(16) __nv_bfloat16 g_h[N_NODES * HIDDEN];  // h' = (X@W)*dinv, bf16
__device__ __align__(16) float g_agg1[N_NODES * HIDDEN];
__device__ __align__(16) float g_agg2[N_NODES * HIDDEN];
__device__ __align__(16) float g_gsum[N_GRAPHS * HIDDEN];
__device__ __align__(16) float g_gcnt[N_GRAPHS];
// CSR scratch
__device__ int g_cnt[N_NODES];
__device__ int g_incl[N_NODES];
__device__ int g_bsum[NBLK];
__device__ int g_bsumx[NBLK];
__device__ int g_off[N_NODES + 1];
__device__ int g_cur[N_NODES];
__device__ __align__(16) int g_ssrc[N_EDGES];

// ---------------- CSR build ---------------------------------------------------
__global__ void k_zero_cnt() {
    int i = blockIdx.x * blockDim.x + threadIdx.x;
    if (i < N_NODES) g_cnt[i] = 0;
}

__global__ void k_hist(const int* __restrict__ dst) {
    int e = blockIdx.x * blockDim.x + threadIdx.x;
    if (e < N_EDGES) atomicAdd(&g_cnt[dst[e]], 1);
}

__global__ void k_scan_local() {
    __shared__ int sm[256];
    int i = blockIdx.x * 256 + threadIdx.x;
    int v = (i < N_NODES) ? g_cnt[i] : 0;
    sm[threadIdx.x] = v;
    __syncthreads();
    #pragma unroll
    for (int ofs = 1; ofs < 256; ofs <<= 1) {
        int t = (threadIdx.x >= ofs) ? sm[threadIdx.x - ofs] : 0;
        __syncthreads();
        sm[threadIdx.x] += t;
        __syncthreads();
    }
    if (i < N_NODES) g_incl[i] = sm[threadIdx.x];
    if (threadIdx.x == 255) g_bsum[blockIdx.x] = sm[255];
}

__global__ void k_scan_blocks() {
    __shared__ int sm[512];
    int t = threadIdx.x;
    int orig = (t < NBLK) ? g_bsum[t] : 0;
    sm[t] = orig;
    __syncthreads();
    #pragma unroll
    for (int ofs = 1; ofs < 512; ofs <<= 1) {
        int v = (t >= ofs) ? sm[t - ofs] : 0;
        __syncthreads();
        sm[t] += v;
        __syncthreads();
    }
    if (t < NBLK) g_bsumx[t] = sm[t] - orig;   // exclusive
    if (t == 0) g_off[N_NODES] = N_EDGES;
}

__global__ void k_finalize() {
    int i = blockIdx.x * blockDim.x + threadIdx.x;
    if (i >= N_NODES) return;
    int c = g_cnt[i];
    int o = g_bsumx[i >> 8] + g_incl[i] - c;
    g_off[i] = o;
    g_cur[i] = o;
    g_dinv[i] = rsqrtf((float)(c + 1));        // +1 self loop
}

__global__ void k_fill(const int* __restrict__ src, const int* __restrict__ dst) {
    int e = blockIdx.x * blockDim.x + threadIdx.x;
    if (e >= N_EDGES) return;
    int d = dst[e];
    int slot = atomicAdd(&g_cur[d], 1);
    g_ssrc[slot] = src[e];
}

// ---------------- GEMM: 64x64 block tile, 4x4 thread tile; bf16 output -------
template <int K, bool RELU>
__global__ void k_gemm(const float* __restrict__ X, const float* __restrict__ W,
                       const float* __restrict__ bias, __nv_bfloat16* __restrict__ Hs) {
    __shared__ float Ws[64][64];
    __shared__ float Xt[64][68];

    const int t = threadIdx.x;
    const int row0 = blockIdx.x * 64;
    const int tc = (t & 15) * 4;
    const int tr = (t >> 4) * 4;

    float acc[4][4] = {};

    for (int k0 = 0; k0 < K; k0 += 64) {
        __syncthreads();
        #pragma unroll 4
        for (int i = t; i < 64 * 64; i += 256) {
            int k = i >> 6, c = i & 63;
            Ws[k][c] = W[(size_t)(k0 + k) * 64 + c];
        }
        #pragma unroll 4
        for (int i = t; i < 64 * 64; i += 256) {
            int r = i >> 6, k = i & 63;
            int gr = row0 + r;
            float v = 0.f;
            if (gr < N_NODES) {
                v = X[(size_t)gr * K + k0 + k];
                if (RELU) v = fmaxf(v + __ldg(&bias[k0 + k]), 0.f);
            }
            Xt[k][r] = v;
        }
        __syncthreads();

        #pragma unroll 16
        for (int k = 0; k < 64; k++) {
            float4 wv = *reinterpret_cast<const float4*>(&Ws[k][tc]);
            float4 xv = *reinterpret_cast<const float4*>(&Xt[k][tr]);
            acc[0][0] += xv.x * wv.x; acc[0][1] += xv.x * wv.y;
            acc[0][2] += xv.x * wv.z; acc[0][3] += xv.x * wv.w;
            acc[1][0] += xv.y * wv.x; acc[1][1] += xv.y * wv.y;
            acc[1][2] += xv.y * wv.z; acc[1][3] += xv.y * wv.w;
            acc[2][0] += xv.z * wv.x; acc[2][1] += xv.z * wv.y;
            acc[2][2] += xv.z * wv.z; acc[2][3] += xv.z * wv.w;
            acc[3][0] += xv.w * wv.x; acc[3][1] += xv.w * wv.y;
            acc[3][2] += xv.w * wv.z; acc[3][3] += xv.w * wv.w;
        }
    }

    #pragma unroll
    for (int i = 0; i < 4; i++) {
        int gr = row0 + tr + i;
        if (gr < N_NODES) {
            float dv = g_dinv[gr];
            __nv_bfloat162 b01 = __float22bfloat162_rn(
                make_float2(acc[i][0] * dv, acc[i][1] * dv));
            __nv_bfloat162 b23 = __float22bfloat162_rn(
                make_float2(acc[i][2] * dv, acc[i][3] * dv));
            uint2 st;
            st.x = *reinterpret_cast<unsigned*>(&b01);
            st.y = *reinterpret_cast<unsigned*>(&b23);
            *reinterpret_cast<uint2*>(&Hs[(size_t)gr * 64 + tc]) = st;
        }
    }
}

// ---------------- pull aggregation -------------------------------------------
// agg[d] = dinv[d] * (h'[d] + sum_{s in nbrs(d)} h'[s]); h' is bf16, acc fp32.
// 8 threads per node (one uint4 = 8 bf16 feats each); indices shuffle-broadcast.
__device__ __forceinline__ void acc_bf8(float* a, uint4 v) {
    float2 f;
    f = __bfloat1622float2(*reinterpret_cast<__nv_bfloat162*>(&v.x)); a[0] += f.x; a[1] += f.y;
    f = __bfloat1622float2(*reinterpret_cast<__nv_bfloat162*>(&v.y)); a[2] += f.x; a[3] += f.y;
    f = __bfloat1622float2(*reinterpret_cast<__nv_bfloat162*>(&v.z)); a[4] += f.x; a[5] += f.y;
    f = __bfloat1622float2(*reinterpret_cast<__nv_bfloat162*>(&v.w)); a[6] += f.x; a[7] += f.y;
}

__global__ void k_gather(const __nv_bfloat16* __restrict__ h, float* __restrict__ agg) {
    int tid = blockIdx.x * blockDim.x + threadIdx.x;
    int node = tid >> 3;
    if (node >= N_NODES) return;
    const int lane = threadIdx.x & 31;
    const int sub = lane & 7;                 // 0..7: which uint4 of the 128B row
    const int gbase = lane & 24;              // group base lane
    const unsigned gmask = 0xFFu << gbase;
    const uint4* hp = reinterpret_cast<const uint4*>(h);  // row = 8 uint4

    int beg = g_off[node];
    int end = g_off[node + 1];

    float a[8] = {};
    acc_bf8(a, hp[(size_t)node * 8 + sub]);   // self term

    for (int j = beg; j < end; j += 8) {
        int n8 = end - j; n8 = n8 > 8 ? 8 : n8;
        int idx = (sub < n8) ? g_ssrc[j + sub] : 0;
        #pragma unroll 8
        for (int t = 0; t < 8; t++) {
            if (t >= n8) break;
            int s = __shfl_sync(gmask, idx, gbase + t, 32);
            acc_bf8(a, hp[(size_t)s * 8 + sub]);
        }
    }

    float dv = g_dinv[node];
    float4 o0 = make_float4(a[0] * dv, a[1] * dv, a[2] * dv, a[3] * dv);
    float4 o1 = make_float4(a[4] * dv, a[5] * dv, a[6] * dv, a[7] * dv);
    float4* op = reinterpret_cast<float4*>(agg + (size_t)node * 64 + sub * 8);
    op[0] = o0;
    op[1] = o1;
}

// ---------------- pooling ----------------------------------------------------
__global__ void k_pool_zero() {
    int i = blockIdx.x * blockDim.x + threadIdx.x;
    if (i < N_GRAPHS * HIDDEN) g_gsum[i] = 0.f;
    if (i < N_GRAPHS) g_gcnt[i] = 0.f;
}

__global__ void k_pool(const int* __restrict__ batch,
                       const float* __restrict__ b2,
                       const float* __restrict__ agg) {
    const int f = threadIdx.x;  // 0..63
    const int chunk = (N_NODES + gridDim.x - 1) / gridDim.x;
    int n0 = blockIdx.x * chunk;
    if (n0 >= N_NODES) return;
    int n1 = min(n0 + chunk, N_NODES);

    const float bf = b2[f];
    int cur = batch[n0];
    float acc = 0.f, cnt = 0.f;
    for (int n = n0; n < n1; n++) {
        int bt = batch[n];
        if (bt != cur) {
            atomicAdd(&g_gsum[cur * HIDDEN + f], acc);
            if (f == 0) atomicAdd(&g_gcnt[cur], cnt);
            acc = 0.f; cnt = 0.f; cur = bt;
        }
        acc += fmaxf(agg[(size_t)n * HIDDEN + f] + bf, 0.f);
        cnt += 1.f;
    }
    atomicAdd(&g_gsum[cur * HIDDEN + f], acc);
    if (f == 0) atomicAdd(&g_gcnt[cur], cnt);
}

// ---------------- head: mean, linear, log_softmax ----------------------------
__global__ void k_head(const float* __restrict__ linW, const float* __restrict__ linb,
                       float* __restrict__ out) {
    int g = threadIdx.x;
    if (g >= N_GRAPHS) return;
    float inv = 1.0f / fmaxf(g_gcnt[g], 1.0f);
    float logits[N_CLASSES];
#pragma unroll
    for (int c = 0; c < N_CLASSES; c++) logits[c] = linb[c];
    for (int f = 0; f < HIDDEN; f++) {
        float p = g_gsum[g * HIDDEN + f] * inv;
#pragma unroll
        for (int c = 0; c < N_CLASSES; c++) logits[c] += p * linW[f * N_CLASSES + c];
    }
    float m = logits[0];
#pragma unroll
    for (int c = 1; c < N_CLASSES; c++) m = fmaxf(m, logits[c]);
    float s = 0.f;
#pragma unroll
    for (int c = 0; c < N_CLASSES; c++) s += expf(logits[c] - m);
    float l = logf(s) + m;
#pragma unroll
    for (int c = 0; c < N_CLASSES; c++) out[g * N_CLASSES + c] = logits[c] - l;
}

// ---------------- launch ------------------------------------------------------
extern "C" void kernel_launch(void* const* d_in, const int* in_sizes, int n_in,
                              void* d_out, int out_size) {
    const float* x     = (const float*)d_in[0];
    const int*   ei    = (const int*)d_in[1];
    const int*   batch = (const int*)d_in[2];
    const float* W1    = (const float*)d_in[3];
    const float* b1    = (const float*)d_in[4];
    const float* W2    = (const float*)d_in[5];
    const float* b2    = (const float*)d_in[6];
    const float* linW  = (const float*)d_in[7];
    const float* linb  = (const float*)d_in[8];
    float* out = (float*)d_out;

    const int* src = ei;
    const int* dst = ei + N_EDGES;

    __nv_bfloat16* p_h;
    float *p_agg1, *p_agg2;
    cudaGetSymbolAddress((void**)&p_h, g_h);
    cudaGetSymbolAddress((void**)&p_agg1, g_agg1);
    cudaGetSymbolAddress((void**)&p_agg2, g_agg2);

    const int NT = 256;
    const int edgeBlocks = (N_EDGES + NT - 1) / NT;
    const int gemmBlocks = (N_NODES + 63) / 64;
    const int gatherBlocks = (N_NODES * 8 + NT - 1) / NT;

    // CSR build (reused by both layers)
    k_zero_cnt<<<NBLK, NT>>>();
    k_hist<<<edgeBlocks, NT>>>(dst);
    k_scan_local<<<NBLK, 256>>>();
    k_scan_blocks<<<1, 512>>>();
    k_finalize<<<NBLK, NT>>>();
    k_fill<<<edgeBlocks, NT>>>(src, dst);

    // layer 1
    k_gemm<D_FEAT, false><<<gemmBlocks, NT>>>(x, W1, nullptr, p_h);
    k_gather<<<gatherBlocks, NT>>>(p_h, p_agg1);

    // layer 2 (relu + b1 fused into GEMM load)
    k_gemm<HIDDEN, true><<<gemmBlocks, NT>>>(p_agg1, W2, b1, p_h);
    k_gather<<<gatherBlocks, NT>>>(p_h, p_agg2);

    // pooling (b2 + relu fused) + head
    k_pool_zero<<<(N_GRAPHS * HIDDEN + NT - 1) / NT, NT>>>();
    k_pool<<<1024, HIDDEN>>>(batch, b2, p_agg2);
    k_head<<<1, N_GRAPHS>>>(linW, linb, out);
}